// round 14
// baseline (speedup 1.0000x reference)
#include <cuda_runtime.h>
#include <cuda_bf16.h>
#include <cuda_pipeline_primitives.h>
#include <cstdint>
#include <math.h>

#define NN 50000
#define EE 625000
#define DD 128
#define MEPS 1e-7f
#define BSTRIDE 64
#define NTILES 391            // ceil(NN/128)

#define ATS   136             // bf16 elements per smem row (128 + 8 pad)
#define ATS_B 272             // row stride bytes

// ---- k_mma dynamic smem byte offsets ----------------------------------------
#define SM_BHI  0
#define SM_BLO  (SM_BHI + 128 * ATS_B)       // 34816
#define SM_A    (SM_BLO + 128 * ATS_B)       // 69632: buf0 hi, buf0 lo, buf1 hi, buf1 lo
#define SM_BIAS (SM_A + 4 * 128 * ATS_B)     // 208896
#define SM_GAM  (SM_BIAS + 512)
#define SM_BET  (SM_GAM + 512)
#define SM_LNP  (SM_BET + 512)               // 128 rows x 4 warps x float2 = 4096
#define SM_TOTAL (SM_LNP + 4096)             // 214528 B

// ================= device scratch =============================================
__device__ __align__(16) float g_h [NN * DD];            // residual state / layer-0 input
__device__ __align__(16) float g_h2[NN * DD];            // relu(LN(h)) next conv input
__device__ __align__(16) __nv_bfloat16 g_Ahi[NN * DD];   // agg output hi (GEMM A)
__device__ __align__(16) __nv_bfloat16 g_Alo[NN * DD];   // agg output lo
__device__ __align__(16) float g_pair[64 * DD];          // (a0,a1) bond table
__device__ __align__(16) float g_b2  [8 * DD];           // bond feature-2 table
__device__ int g_cursor[NN];
__device__ int g_packed[NN * BSTRIDE];                   // src(16b)|a0<<16|a1<<19|a2<<22

// ================= helpers ====================================================
__device__ __forceinline__ uint32_t smem_to_u32(const void* smem_ptr) {
    uint32_t addr;
    asm("{ .reg .u64 tmp; cvta.to.shared.u64 tmp, %1; cvt.u32.u64 %0, tmp; }"
        : "=r"(addr) : "l"(smem_ptr));
    return addr;
}

__device__ __forceinline__ void ldsm4(uint32_t& r0, uint32_t& r1, uint32_t& r2,
                                      uint32_t& r3, uint32_t addr) {
    asm volatile("ldmatrix.sync.aligned.m8n8.x4.shared.b16 {%0,%1,%2,%3}, [%4];"
                 : "=r"(r0), "=r"(r1), "=r"(r2), "=r"(r3) : "r"(addr));
}

__device__ __forceinline__ void mma_bf16(float& d0, float& d1, float& d2, float& d3,
                                         uint32_t a0, uint32_t a1, uint32_t a2, uint32_t a3,
                                         uint32_t b0, uint32_t b1) {
    asm volatile("mma.sync.aligned.m16n8k16.row.col.f32.bf16.bf16.f32 "
                 "{%0,%1,%2,%3}, {%4,%5,%6,%7}, {%8,%9}, {%0,%1,%2,%3};"
                 : "+f"(d0), "+f"(d1), "+f"(d2), "+f"(d3)
                 : "r"(a0), "r"(a1), "r"(a2), "r"(a3), "r"(b0), "r"(b1));
}

__device__ __forceinline__ unsigned pack2(__nv_bfloat16 a, __nv_bfloat16 b) {
    __nv_bfloat162 t = __halves2bfloat162(a, b);
    return *reinterpret_cast<unsigned*>(&t);
}
__device__ __forceinline__ void bsplit(float v, __nv_bfloat16& hi, __nv_bfloat16& lo) {
    hi = __float2bfloat16(v);
    lo = __float2bfloat16(v - __bfloat162float(hi));
}

// ================= prep =======================================================
__global__ void k_atom(const int* __restrict__ x, const float* __restrict__ aemb,
                       const float* __restrict__ bemb) {
    int i = blockIdx.x * blockDim.x + threadIdx.x;   // NN*32 float4 slots
    if (i >= NN * 32) return;
    int n = i >> 5, q = i & 31;
    if (q == 0) g_cursor[n] = 0;
    if (i < 64 * 32) {                               // pair table: c = a0 | a1<<3
        int c = i >> 5, qq = i & 31;
        float4 u = ((const float4*)(bemb + ((c & 7)     ) * DD))[qq];
        float4 v = ((const float4*)(bemb + (8 + (c >> 3)) * DD))[qq];
        ((float4*)(g_pair + c * DD))[qq] =
            make_float4(u.x + v.x, u.y + v.y, u.z + v.z, u.w + v.w);
    }
    if (i < 8 * 32)
        ((float4*)g_b2)[i] = ((const float4*)(bemb + 16 * DD))[i];
    float4 s = make_float4(0.f, 0.f, 0.f, 0.f);
#pragma unroll
    for (int f = 0; f < 9; ++f) {
        int v = x[n * 9 + f];
        float4 t = ((const float4*)(aemb + (f * 64 + v) * DD))[q];
        s.x += t.x; s.y += t.y; s.z += t.z; s.w += t.w;
    }
    ((float4*)(g_h + n * DD))[q] = s;
}

__global__ void k_scatter(const int* __restrict__ src, const int* __restrict__ dst,
                          const int* __restrict__ ea) {
    int e = blockIdx.x * blockDim.x + threadIdx.x;
    if (e >= EE) return;
    int d = dst[e];
    int pos = atomicAdd(&g_cursor[d], 1);
    if (pos < BSTRIDE) {
        int p = src[e] | (ea[e * 3] << 16) | (ea[e * 3 + 1] << 19) | (ea[e * 3 + 2] << 22);
        g_packed[d * BSTRIDE + pos] = p;
    }
}

// ================= aggregation (persistent, warp/node, SCALAR math) ===========
__global__ void __launch_bounds__(256, 5) k_agg(const float* __restrict__ hin) {
    __shared__ float SP[64 * DD];
    __shared__ float S2[8 * DD];
    int tid = threadIdx.x;
    for (int i = tid; i < 64 * 32; i += 256) ((float4*)SP)[i] = ((const float4*)g_pair)[i];
    if (tid < 8 * 32) ((float4*)S2)[tid] = ((const float4*)g_b2)[tid];
    __syncthreads();

    int warp = tid >> 5, lane = tid & 31;
    const float4* SPl = (const float4*)SP + lane;
    const float4* S2l = (const float4*)S2 + lane;
    const float4* Hl  = (const float4*)hin + lane;

    for (int n = blockIdx.x * 8 + warp; n < NN; n += gridDim.x * 8) {
        int deg = g_cursor[n]; if (deg > BSTRIDE) deg = BSTRIDE;
        int base = n * BSTRIDE;
        int pk0 = g_packed[base + lane];
        int pk1 = g_packed[base + 32 + lane];

        float dn0 = 0.f, dn1 = 0.f, dn2 = 0.f, dn3 = 0.f;
        float nm0 = 0.f, nm1 = 0.f, nm2 = 0.f, nm3 = 0.f;

        // exp(m̂+eps) factors cancel in num/den; add eps once at the end (exact).
        auto proc = [&](int p) {
            const float4 hv = __ldg(Hl + (p & 0xFFFF) * 32);
            const float4 c  = SPl[((p >> 16) & 63) * 32];
            const float4 d  = S2l[((p >> 22) & 7) * 32];
            float m0 = fmaxf(hv.x + c.x + d.x, 0.f);
            float m1 = fmaxf(hv.y + c.y + d.y, 0.f);
            float m2 = fmaxf(hv.z + c.z + d.z, 0.f);
            float m3 = fmaxf(hv.w + c.w + d.w, 0.f);
            float e0 = __expf(m0), e1 = __expf(m1);
            float e2 = __expf(m2), e3 = __expf(m3);
            dn0 += e0; dn1 += e1; dn2 += e2; dn3 += e3;
            nm0 = fmaf(e0, m0, nm0); nm1 = fmaf(e1, m1, nm1);
            nm2 = fmaf(e2, m2, nm2); nm3 = fmaf(e3, m3, nm3);
        };

        int pairs = deg & ~1;
        for (int i = 0; i < pairs; i += 2) {
            int p0 = __shfl_sync(0xffffffffu, (i < 32) ? pk0 : pk1, i & 31);
            int j = i + 1;
            int p1 = __shfl_sync(0xffffffffu, (j < 32) ? pk0 : pk1, j & 31);
            proc(p0);
            proc(p1);
        }
        if (deg & 1) {
            int p = __shfl_sync(0xffffffffu, (pairs < 32) ? pk0 : pk1, pairs & 31);
            proc(p);
        }

        float4 hn = __ldg(Hl + n * 32);
        float4 o;
        o.x = hn.x + nm0 / (dn0 + 1e-16f) + MEPS;
        o.y = hn.y + nm1 / (dn1 + 1e-16f) + MEPS;
        o.z = hn.z + nm2 / (dn2 + 1e-16f) + MEPS;
        o.w = hn.w + nm3 / (dn3 + 1e-16f) + MEPS;

        __nv_bfloat16 h0, h1, h2, h3, l0, l1, l2, l3;
        bsplit(o.x, h0, l0); bsplit(o.y, h1, l1);
        bsplit(o.z, h2, l2); bsplit(o.w, h3, l3);
        uint2 uh, ul;
        uh.x = pack2(h0, h1); uh.y = pack2(h2, h3);
        ul.x = pack2(l0, l1); ul.y = pack2(l2, l3);
        ((uint2*)(g_Ahi + n * DD))[lane] = uh;
        ((uint2*)(g_Alo + n * DD))[lane] = ul;
    }
}

// ================= HMMA GEMM layer (R9 champion, verbatim) ====================
template <bool RES, bool FINAL>
__global__ void __launch_bounds__(512, 1) k_mma(const float* __restrict__ Wl,
                                                const float* __restrict__ bl,
                                                const float* __restrict__ gl,
                                                const float* __restrict__ btl,
                                                float* __restrict__ dout) {
    extern __shared__ char smc[];
    uint32_t sb = smem_to_u32(smc);
    int tid = threadIdx.x;
    int warp = tid >> 5, lane = tid & 31;
    int wm = warp >> 2, wn = warp & 3;      // 4x4 warp grid: 32-row x 32-col warp tiles

    // ---- prologue: W transpose+split into B[n][k], bias/gamma/beta, first A --
    for (int i = tid; i < 128 * 32; i += 512) {
        int k = i >> 5, q = i & 31;
        float4 w = *(const float4*)&Wl[k * DD + q * 4];
#pragma unroll
        for (int e = 0; e < 4; ++e) {
            int n = q * 4 + e;
            float val = (e == 0) ? w.x : (e == 1) ? w.y : (e == 2) ? w.z : w.w;
            __nv_bfloat16 hi, lo;
            bsplit(val, hi, lo);
            ((__nv_bfloat16*)(smc + SM_BHI))[n * ATS + k] = hi;
            ((__nv_bfloat16*)(smc + SM_BLO))[n * ATS + k] = lo;
        }
    }
    for (int i = tid; i < 128; i += 512) {
        ((float*)(smc + SM_BIAS))[i] = bl[i];
        ((float*)(smc + SM_GAM))[i]  = gl[i];
        ((float*)(smc + SM_BET))[i]  = btl[i];
    }
    // prefetch first A tile into buf0
    {
        int t0 = blockIdx.x;
        if (t0 < NTILES) {
            int row0 = t0 * 128;
            char* dsth = smc + SM_A;
            char* dstl = dsth + 128 * ATS_B;
            for (int i = tid; i < 128 * 16; i += 512) {
                int r = i >> 4, ch = (i & 15) * 16;
                int grow = row0 + r;
                int gz = (grow < NN) ? 0 : 16;
                int gr = (grow < NN) ? grow : 0;
                __pipeline_memcpy_async(dsth + r * ATS_B + ch,
                                        (const char*)(g_Ahi + gr * DD) + ch, 16, gz);
                __pipeline_memcpy_async(dstl + r * ATS_B + ch,
                                        (const char*)(g_Alo + gr * DD) + ch, 16, gz);
            }
        }
    }
    __pipeline_commit();
    __syncthreads();

    // ldmatrix per-lane offsets (proven R9 mappings)
    uint32_t a_loff = (uint32_t)(((lane & 15) * ATS + (lane >> 4) * 8) * 2);
    uint32_t b_loff = (uint32_t)((((lane & 7) + ((lane >> 4) & 1) * 8) * ATS
                                  + ((lane >> 3) & 1) * 8) * 2);
    uint32_t bhi_base = sb + SM_BHI + (uint32_t)(wn * 32 * ATS_B) + b_loff;
    uint32_t blo_base = sb + SM_BLO + (uint32_t)(wn * 32 * ATS_B) + b_loff;

    const float* bias = (const float*)(smc + SM_BIAS);
    const float* gam  = (const float*)(smc + SM_GAM);
    const float* bet  = (const float*)(smc + SM_BET);
    float2* lnp       = (float2*)(smc + SM_LNP);

    int l23 = lane >> 2;
    int lc  = (lane & 3) * 2;

    int buf = 0;
    for (int t = blockIdx.x; t < NTILES; t += gridDim.x) {
        int row0 = t * 128;
        __pipeline_wait_prior(0);
        __syncthreads();

        int tn = t + (int)gridDim.x;
        if (tn < NTILES) {
            int row0n = tn * 128;
            char* dsth = smc + SM_A + (buf ^ 1) * (2 * 128 * ATS_B);
            char* dstl = dsth + 128 * ATS_B;
            for (int i = tid; i < 128 * 16; i += 512) {
                int r = i >> 4, ch = (i & 15) * 16;
                int grow = row0n + r;
                int gz = (grow < NN) ? 0 : 16;
                int gr = (grow < NN) ? grow : 0;
                __pipeline_memcpy_async(dsth + r * ATS_B + ch,
                                        (const char*)(g_Ahi + gr * DD) + ch, 16, gz);
                __pipeline_memcpy_async(dstl + r * ATS_B + ch,
                                        (const char*)(g_Alo + gr * DD) + ch, 16, gz);
            }
        }
        __pipeline_commit();

        uint32_t abase_hi = sb + SM_A + (uint32_t)(buf * 2 * 128 * ATS_B) + a_loff
                          + (uint32_t)(wm * 32 * ATS_B);
        uint32_t abase_lo = abase_hi + (uint32_t)(128 * ATS_B);

        float acc[2][4][4];
#pragma unroll
        for (int mt = 0; mt < 2; ++mt)
#pragma unroll
            for (int nt = 0; nt < 4; ++nt)
#pragma unroll
                for (int e = 0; e < 4; ++e) acc[mt][nt][e] = 0.f;

#pragma unroll
        for (int ks = 0; ks < 8; ++ks) {
            uint32_t kofs = (uint32_t)(ks * 32);
            uint32_t bh00, bh01, bh02, bh03, bh10, bh11, bh12, bh13;
            uint32_t bl00, bl01, bl02, bl03, bl10, bl11, bl12, bl13;
            ldsm4(bh00, bh01, bh02, bh03, bhi_base + kofs);
            ldsm4(bh10, bh11, bh12, bh13, bhi_base + 16 * ATS_B + kofs);
            ldsm4(bl00, bl01, bl02, bl03, blo_base + kofs);
            ldsm4(bl10, bl11, bl12, bl13, blo_base + 16 * ATS_B + kofs);
#pragma unroll
            for (int mt = 0; mt < 2; ++mt) {
                uint32_t arow = (uint32_t)(mt * 16 * ATS_B) + kofs;
                uint32_t ah0, ah1, ah2, ah3, al0, al1, al2, al3;
                ldsm4(ah0, ah1, ah2, ah3, abase_hi + arow);
                ldsm4(al0, al1, al2, al3, abase_lo + arow);
                mma_bf16(acc[mt][0][0], acc[mt][0][1], acc[mt][0][2], acc[mt][0][3],
                         ah0, ah1, ah2, ah3, bh00, bh01);
                mma_bf16(acc[mt][0][0], acc[mt][0][1], acc[mt][0][2], acc[mt][0][3],
                         ah0, ah1, ah2, ah3, bl00, bl01);
                mma_bf16(acc[mt][0][0], acc[mt][0][1], acc[mt][0][2], acc[mt][0][3],
                         al0, al1, al2, al3, bh00, bh01);
                mma_bf16(acc[mt][1][0], acc[mt][1][1], acc[mt][1][2], acc[mt][1][3],
                         ah0, ah1, ah2, ah3, bh02, bh03);
                mma_bf16(acc[mt][1][0], acc[mt][1][1], acc[mt][1][2], acc[mt][1][3],
                         ah0, ah1, ah2, ah3, bl02, bl03);
                mma_bf16(acc[mt][1][0], acc[mt][1][1], acc[mt][1][2], acc[mt][1][3],
                         al0, al1, al2, al3, bh02, bh03);
                mma_bf16(acc[mt][2][0], acc[mt][2][1], acc[mt][2][2], acc[mt][2][3],
                         ah0, ah1, ah2, ah3, bh10, bh11);
                mma_bf16(acc[mt][2][0], acc[mt][2][1], acc[mt][2][2], acc[mt][2][3],
                         ah0, ah1, ah2, ah3, bl10, bl11);
                mma_bf16(acc[mt][2][0], acc[mt][2][1], acc[mt][2][2], acc[mt][2][3],
                         al0, al1, al2, al3, bh10, bh11);
                mma_bf16(acc[mt][3][0], acc[mt][3][1], acc[mt][3][2], acc[mt][3][3],
                         ah0, ah1, ah2, ah3, bh12, bh13);
                mma_bf16(acc[mt][3][0], acc[mt][3][1], acc[mt][3][2], acc[mt][3][3],
                         ah0, ah1, ah2, ah3, bl12, bl13);
                mma_bf16(acc[mt][3][0], acc[mt][3][1], acc[mt][3][2], acc[mt][3][3],
                         al0, al1, al2, al3, bh12, bh13);
            }
        }

        // ---- epilogue: bias (+residual), LN partials, normalize, store ----
#pragma unroll
        for (int mt = 0; mt < 2; ++mt) {
            int rl0 = wm * 32 + mt * 16 + l23;
            int rl1 = rl0 + 8;
            int gr0 = row0 + rl0, gr1 = row0 + rl1;
            int gc0 = (gr0 < NN) ? gr0 : 0;
            int gc1 = (gr1 < NN) ? gr1 : 0;
            float s0 = 0.f, q0 = 0.f, s1 = 0.f, q1 = 0.f;
#pragma unroll
            for (int nt = 0; nt < 4; ++nt) {
                int c = wn * 32 + nt * 8 + lc;
                float2 bv = *(const float2*)(bias + c);
                float v0 = acc[mt][nt][0] + bv.x;
                float v1 = acc[mt][nt][1] + bv.y;
                float v2 = acc[mt][nt][2] + bv.x;
                float v3 = acc[mt][nt][3] + bv.y;
                if (RES) {
                    float2 r0 = *(const float2*)&g_h[gc0 * DD + c];
                    float2 r1 = *(const float2*)&g_h[gc1 * DD + c];
                    v0 += r0.x; v1 += r0.y; v2 += r1.x; v3 += r1.y;
                }
                acc[mt][nt][0] = v0; acc[mt][nt][1] = v1;
                acc[mt][nt][2] = v2; acc[mt][nt][3] = v3;
                s0 += v0 + v1; q0 += v0 * v0 + v1 * v1;
                s1 += v2 + v3; q1 += v2 * v2 + v3 * v3;
            }
            s0 += __shfl_xor_sync(0xffffffffu, s0, 1); s0 += __shfl_xor_sync(0xffffffffu, s0, 2);
            q0 += __shfl_xor_sync(0xffffffffu, q0, 1); q0 += __shfl_xor_sync(0xffffffffu, q0, 2);
            s1 += __shfl_xor_sync(0xffffffffu, s1, 1); s1 += __shfl_xor_sync(0xffffffffu, s1, 2);
            q1 += __shfl_xor_sync(0xffffffffu, q1, 1); q1 += __shfl_xor_sync(0xffffffffu, q1, 2);
            if ((lane & 3) == 0) {
                lnp[rl0 * 4 + wn] = make_float2(s0, q0);
                lnp[rl1 * 4 + wn] = make_float2(s1, q1);
            }
        }
        __syncthreads();

#pragma unroll
        for (int mt = 0; mt < 2; ++mt) {
            int rl0 = wm * 32 + mt * 16 + l23;
            int rl1 = rl0 + 8;
            int gr0 = row0 + rl0, gr1 = row0 + rl1;
            float S0 = 0.f, Q0 = 0.f, S1 = 0.f, Q1 = 0.f;
#pragma unroll
            for (int w = 0; w < 4; ++w) {
                float2 p0 = lnp[rl0 * 4 + w]; S0 += p0.x; Q0 += p0.y;
                float2 p1 = lnp[rl1 * 4 + w]; S1 += p1.x; Q1 += p1.y;
            }
            float mu0 = S0 * (1.f / 128.f), mu1 = S1 * (1.f / 128.f);
            float rs0 = rsqrtf(Q0 * (1.f / 128.f) - mu0 * mu0 + 1e-5f);
            float rs1 = rsqrtf(Q1 * (1.f / 128.f) - mu1 * mu1 + 1e-5f);
#pragma unroll
            for (int nt = 0; nt < 4; ++nt) {
                int c = wn * 32 + nt * 8 + lc;
                float2 gv = *(const float2*)(gam + c);
                float2 tv = *(const float2*)(bet + c);
                float v0 = acc[mt][nt][0], v1 = acc[mt][nt][1];
                float v2 = acc[mt][nt][2], v3 = acc[mt][nt][3];
                float y0 = (v0 - mu0) * rs0 * gv.x + tv.x;
                float y1 = (v1 - mu0) * rs0 * gv.y + tv.y;
                float y2 = (v2 - mu1) * rs1 * gv.x + tv.x;
                float y3 = (v3 - mu1) * rs1 * gv.y + tv.y;
                if (gr0 < NN) {
                    if (FINAL) {
                        *(float2*)&dout[gr0 * DD + c] = make_float2(y0, y1);
                    } else {
                        *(float2*)&g_h [gr0 * DD + c] = make_float2(v0, v1);
                        *(float2*)&g_h2[gr0 * DD + c] = make_float2(fmaxf(y0, 0.f), fmaxf(y1, 0.f));
                    }
                }
                if (gr1 < NN) {
                    if (FINAL) {
                        *(float2*)&dout[gr1 * DD + c] = make_float2(y2, y3);
                    } else {
                        *(float2*)&g_h [gr1 * DD + c] = make_float2(v2, v3);
                        *(float2*)&g_h2[gr1 * DD + c] = make_float2(fmaxf(y2, 0.f), fmaxf(y3, 0.f));
                    }
                }
            }
        }
        buf ^= 1;
        __syncthreads();
    }
}

// ================= launch =====================================================
extern "C" void kernel_launch(void* const* d_in, const int* in_sizes, int n_in,
                              void* d_out, int out_size) {
    const int*   x    = (const int*)  d_in[0];
    const int*   ei   = (const int*)  d_in[1];
    const int*   ea   = (const int*)  d_in[2];
    const float* aemb = (const float*)d_in[3];
    const float* bemb = (const float*)d_in[4];
    const float* W    = (const float*)d_in[5];
    const float* b    = (const float*)d_in[6];
    const float* g    = (const float*)d_in[7];
    const float* bt   = (const float*)d_in[8];
    float* out = (float*)d_out;
    const int* src = ei;
    const int* dst = ei + EE;

    static float *p_h = nullptr, *p_h2 = nullptr;
    static int sms = 148;
    if (!p_h) {
        cudaGetSymbolAddress((void**)&p_h,  g_h);
        cudaGetSymbolAddress((void**)&p_h2, g_h2);
        cudaDeviceGetAttribute(&sms, cudaDevAttrMultiProcessorCount, 0);
        cudaFuncSetAttribute((const void*)k_mma<false, false>, cudaFuncAttributeMaxDynamicSharedMemorySize, SM_TOTAL);
        cudaFuncSetAttribute((const void*)k_mma<true,  false>, cudaFuncAttributeMaxDynamicSharedMemorySize, SM_TOTAL);
        cudaFuncSetAttribute((const void*)k_mma<true,  true >, cudaFuncAttributeMaxDynamicSharedMemorySize, SM_TOTAL);
    }

    k_atom<<<(NN * 32 + 255) / 256, 256>>>(x, aemb, bemb);     // launch 0
    k_scatter<<<(EE + 255) / 256, 256>>>(src, dst, ea);        // launch 1

    int agg_blocks = sms * 5;
    for (int l = 0; l < 7; ++l) {
        const float* Wl  = W  + l * DD * DD;
        const float* bl  = b  + l * DD;
        const float* gl  = g  + l * DD;
        const float* btl = bt + l * DD;
        const float* hi = (l == 0) ? p_h : p_h2;
        k_agg<<<agg_blocks, 256>>>(hi);                        // launch 2 = agg0
        if (l == 0)
            k_mma<false, false><<<sms, 512, SM_TOTAL>>>(Wl, bl, gl, btl, out);  // launch 3 (profiled)
        else if (l < 6)
            k_mma<true, false><<<sms, 512, SM_TOTAL>>>(Wl, bl, gl, btl, out);
        else
            k_mma<true, true><<<sms, 512, SM_TOTAL>>>(Wl, bl, gl, btl, out);
    }
}

// round 16
// speedup vs baseline: 1.1525x; 1.1525x over previous
#include <cuda_runtime.h>
#include <cuda_bf16.h>
#include <cuda_pipeline_primitives.h>
#include <cstdint>
#include <math.h>

#define NN 50000
#define EE 625000
#define DD 128
#define MEPS 1e-7f
#define BSTRIDE 64
#define NTILES 391            // ceil(NN/128)

#define ATS   136             // bf16 elements per smem row (128 + 8 pad)
#define ATS_B 272             // row stride bytes (= 17 * 16)

// ---- k_mma dynamic smem byte offsets ----------------------------------------
#define SM_BHI  0
#define SM_BLO  (SM_BHI + 128 * ATS_B)       // 34816
#define SM_A    (SM_BLO + 128 * ATS_B)       // 69632: buf0 hi, buf0 lo, buf1 hi, buf1 lo
#define SM_BIAS (SM_A + 4 * 128 * ATS_B)     // 208896
#define SM_GAM  (SM_BIAS + 512)
#define SM_BET  (SM_GAM + 512)
#define SM_LNP  (SM_BET + 512)               // 128 rows x 4 warps x float2 = 4096
#define SM_TOTAL (SM_LNP + 4096)             // 214528 B

// ================= device scratch =============================================
__device__ __align__(16) float g_h [NN * DD];            // residual state / layer-0 input
__device__ __align__(16) float g_h2[NN * DD];            // relu(LN(h)) next conv input
__device__ __align__(16) __nv_bfloat16 g_Ahi[NN * DD];   // agg output hi (GEMM A)
__device__ __align__(16) __nv_bfloat16 g_Alo[NN * DD];   // agg output lo
__device__ __align__(16) __nv_bfloat16 g_Whi[7 * 128 * ATS];  // presplit W hi, padded rows
__device__ __align__(16) __nv_bfloat16 g_Wlo[7 * 128 * ATS];  // presplit W lo
__device__ __align__(16) float g_pair[64 * DD];          // (a0,a1) bond table
__device__ __align__(16) float g_b2  [8 * DD];           // bond feature-2 table
__device__ int g_cursor[NN];
__device__ int g_packed[NN * BSTRIDE];                   // src(16b)|a0<<16|a1<<19|a2<<22

// ================= helpers ====================================================
__device__ __forceinline__ uint32_t smem_to_u32(const void* smem_ptr) {
    uint32_t addr;
    asm("{ .reg .u64 tmp; cvta.to.shared.u64 tmp, %1; cvt.u32.u64 %0, tmp; }"
        : "=r"(addr) : "l"(smem_ptr));
    return addr;
}

__device__ __forceinline__ void ldsm4(uint32_t& r0, uint32_t& r1, uint32_t& r2,
                                      uint32_t& r3, uint32_t addr) {
    asm volatile("ldmatrix.sync.aligned.m8n8.x4.shared.b16 {%0,%1,%2,%3}, [%4];"
                 : "=r"(r0), "=r"(r1), "=r"(r2), "=r"(r3) : "r"(addr));
}

__device__ __forceinline__ void mma_bf16(float& d0, float& d1, float& d2, float& d3,
                                         uint32_t a0, uint32_t a1, uint32_t a2, uint32_t a3,
                                         uint32_t b0, uint32_t b1) {
    asm volatile("mma.sync.aligned.m16n8k16.row.col.f32.bf16.bf16.f32 "
                 "{%0,%1,%2,%3}, {%4,%5,%6,%7}, {%8,%9}, {%0,%1,%2,%3};"
                 : "+f"(d0), "+f"(d1), "+f"(d2), "+f"(d3)
                 : "r"(a0), "r"(a1), "r"(a2), "r"(a3), "r"(b0), "r"(b1));
}

__device__ __forceinline__ unsigned long long f2u(float2 v) {
    return *reinterpret_cast<unsigned long long*>(&v);
}
__device__ __forceinline__ float2 u2f2(unsigned long long v) {
    return *reinterpret_cast<float2*>(&v);
}
__device__ __forceinline__ float2 f2add(float2 a, float2 b) {
    unsigned long long d;
    asm("add.rn.f32x2 %0,%1,%2;" : "=l"(d) : "l"(f2u(a)), "l"(f2u(b)));
    return u2f2(d);
}
__device__ __forceinline__ float2 f2fma(float2 a, float2 b, float2 c) {
    unsigned long long d;
    asm("fma.rn.f32x2 %0,%1,%2,%3;" : "=l"(d) : "l"(f2u(a)), "l"(f2u(b)), "l"(f2u(c)));
    return u2f2(d);
}

__device__ __forceinline__ unsigned pack2(__nv_bfloat16 a, __nv_bfloat16 b) {
    __nv_bfloat162 t = __halves2bfloat162(a, b);
    return *reinterpret_cast<unsigned*>(&t);
}
__device__ __forceinline__ void bsplit(float v, __nv_bfloat16& hi, __nv_bfloat16& lo) {
    hi = __float2bfloat16(v);
    lo = __float2bfloat16(v - __bfloat162float(hi));
}

// ================= prep =======================================================
__global__ void k_atom(const int* __restrict__ x, const float* __restrict__ aemb,
                       const float* __restrict__ bemb) {
    int i = blockIdx.x * blockDim.x + threadIdx.x;   // NN*32 float4 slots
    if (i >= NN * 32) return;
    int n = i >> 5, q = i & 31;
    if (q == 0) g_cursor[n] = 0;
    if (i < 64 * 32) {                               // pair table: c = a0 | a1<<3
        int c = i >> 5, qq = i & 31;
        float4 u = ((const float4*)(bemb + ((c & 7)     ) * DD))[qq];
        float4 v = ((const float4*)(bemb + (8 + (c >> 3)) * DD))[qq];
        ((float4*)(g_pair + c * DD))[qq] =
            make_float4(u.x + v.x, u.y + v.y, u.z + v.z, u.w + v.w);
    }
    if (i < 8 * 32)
        ((float4*)g_b2)[i] = ((const float4*)(bemb + 16 * DD))[i];
    float4 s = make_float4(0.f, 0.f, 0.f, 0.f);
#pragma unroll
    for (int f = 0; f < 9; ++f) {
        int v = x[n * 9 + f];
        float4 t = ((const float4*)(aemb + (f * 64 + v) * DD))[q];
        s.x += t.x; s.y += t.y; s.z += t.z; s.w += t.w;
    }
    ((float4*)(g_h + n * DD))[q] = s;
}

__global__ void k_scatter(const int* __restrict__ src, const int* __restrict__ dst,
                          const int* __restrict__ ea) {
    int e = blockIdx.x * blockDim.x + threadIdx.x;
    if (e >= EE) return;
    int d = dst[e];
    int pos = atomicAdd(&g_cursor[d], 1);
    if (pos < BSTRIDE) {
        int p = src[e] | (ea[e * 3] << 16) | (ea[e * 3 + 1] << 19) | (ea[e * 3 + 2] << 22);
        g_packed[d * BSTRIDE + pos] = p;
    }
}

// presplit all 7 W matrices into [n][k] padded bf16 hi/lo (smem-image layout)
__global__ void k_wsplit(const float* __restrict__ W) {
    int i = blockIdx.x * blockDim.x + threadIdx.x;   // 7*128*32
    if (i >= 7 * 128 * 32) return;
    int l = i / (128 * 32);
    int r = i % (128 * 32);
    int n = r >> 5, kq = (r & 31) * 4;
    const float* Wl = W + l * DD * DD;
    __nv_bfloat16 hi[4], lo[4];
#pragma unroll
    for (int e = 0; e < 4; ++e) {
        float v = Wl[(kq + e) * DD + n];             // W[k][n] -> B[n][k]
        bsplit(v, hi[e], lo[e]);
    }
    uint2 uh, ul;
    uh.x = pack2(hi[0], hi[1]); uh.y = pack2(hi[2], hi[3]);
    ul.x = pack2(lo[0], lo[1]); ul.y = pack2(lo[2], lo[3]);
    *(uint2*)&g_Whi[(l * 128 + n) * ATS + kq] = uh;
    *(uint2*)&g_Wlo[(l * 128 + n) * ATS + kq] = ul;
}

// ================= aggregation (R9 champion, verbatim: packed f32x2) ==========
__global__ void __launch_bounds__(256, 5) k_agg(const float* __restrict__ hin) {
    __shared__ float SP[64 * DD];
    __shared__ float S2[8 * DD];
    int tid = threadIdx.x;
    for (int i = tid; i < 64 * 32; i += 256) ((float4*)SP)[i] = ((const float4*)g_pair)[i];
    if (tid < 8 * 32) ((float4*)S2)[tid] = ((const float4*)g_b2)[tid];
    __syncthreads();

    int warp = tid >> 5, lane = tid & 31;
    const float4* SPl = (const float4*)SP + lane;
    const float4* S2l = (const float4*)S2 + lane;
    const float4* Hl  = (const float4*)hin + lane;
    const float2 eps2 = make_float2(MEPS, MEPS);

    for (int n = blockIdx.x * 8 + warp; n < NN; n += gridDim.x * 8) {
        int deg = g_cursor[n]; if (deg > BSTRIDE) deg = BSTRIDE;
        int base = n * BSTRIDE;
        int pk0 = g_packed[base + lane];
        int pk1 = g_packed[base + 32 + lane];

        float2 den01 = make_float2(0.f, 0.f), den23 = make_float2(0.f, 0.f);
        float2 num01 = make_float2(0.f, 0.f), num23 = make_float2(0.f, 0.f);

        auto proc = [&](int p) {
            const float4 hv = __ldg(Hl + (p & 0xFFFF) * 32);
            const float4 c  = SPl[((p >> 16) & 63) * 32];
            const float4 d  = S2l[((p >> 22) & 7) * 32];
            float2 t01 = f2add(make_float2(hv.x, hv.y), make_float2(c.x, c.y));
            float2 t23 = f2add(make_float2(hv.z, hv.w), make_float2(c.z, c.w));
            t01 = f2add(t01, make_float2(d.x, d.y));
            t23 = f2add(t23, make_float2(d.z, d.w));
            float2 m01 = f2add(make_float2(fmaxf(t01.x, 0.f), fmaxf(t01.y, 0.f)), eps2);
            float2 m23 = f2add(make_float2(fmaxf(t23.x, 0.f), fmaxf(t23.y, 0.f)), eps2);
            float2 e01 = make_float2(__expf(m01.x), __expf(m01.y));
            float2 e23 = make_float2(__expf(m23.x), __expf(m23.y));
            den01 = f2add(den01, e01);  den23 = f2add(den23, e23);
            num01 = f2fma(e01, m01, num01);  num23 = f2fma(e23, m23, num23);
        };

        int pairs = deg & ~1;
        for (int i = 0; i < pairs; i += 2) {
            int p0 = __shfl_sync(0xffffffffu, (i < 32) ? pk0 : pk1, i & 31);
            int j = i + 1;
            int p1 = __shfl_sync(0xffffffffu, (j < 32) ? pk0 : pk1, j & 31);
            proc(p0);
            proc(p1);
        }
        if (deg & 1) {
            int p = __shfl_sync(0xffffffffu, (pairs < 32) ? pk0 : pk1, pairs & 31);
            proc(p);
        }

        float4 hn = __ldg(Hl + n * 32);
        float4 o;
        o.x = hn.x + num01.x / (den01.x + 1e-16f);
        o.y = hn.y + num01.y / (den01.y + 1e-16f);
        o.z = hn.z + num23.x / (den23.x + 1e-16f);
        o.w = hn.w + num23.y / (den23.y + 1e-16f);

        __nv_bfloat16 h0, h1, h2, h3, l0, l1, l2, l3;
        bsplit(o.x, h0, l0); bsplit(o.y, h1, l1);
        bsplit(o.z, h2, l2); bsplit(o.w, h3, l3);
        uint2 uh, ul;
        uh.x = pack2(h0, h1); uh.y = pack2(h2, h3);
        ul.x = pack2(l0, l1); ul.y = pack2(l2, l3);
        ((uint2*)(g_Ahi + n * DD))[lane] = uh;
        ((uint2*)(g_Alo + n * DD))[lane] = ul;
    }
}

// ================= HMMA GEMM layer (R9 + cp.async W prologue) =================
template <bool RES, bool FINAL>
__global__ void __launch_bounds__(512, 1) k_mma(const __nv_bfloat16* __restrict__ Whi,
                                                const __nv_bfloat16* __restrict__ Wlo,
                                                const float* __restrict__ bl,
                                                const float* __restrict__ gl,
                                                const float* __restrict__ btl,
                                                float* __restrict__ dout) {
    extern __shared__ char smc[];
    uint32_t sb = smem_to_u32(smc);
    int tid = threadIdx.x;
    int warp = tid >> 5, lane = tid & 31;
    int wm = warp >> 2, wn = warp & 3;      // 4x4 warp grid: 32-row x 32-col warp tiles

    // ---- prologue: cp.async presplit W + params + first A tile --------------
    for (int i = tid; i < 128 * 17; i += 512) {
        int r = i / 17, ch = (i % 17) * 16;
        __pipeline_memcpy_async(smc + SM_BHI + r * ATS_B + ch,
                                (const char*)Whi + r * ATS_B + ch, 16, 0);
        __pipeline_memcpy_async(smc + SM_BLO + r * ATS_B + ch,
                                (const char*)Wlo + r * ATS_B + ch, 16, 0);
    }
    for (int i = tid; i < 128; i += 512) {
        ((float*)(smc + SM_BIAS))[i] = bl[i];
        ((float*)(smc + SM_GAM))[i]  = gl[i];
        ((float*)(smc + SM_BET))[i]  = btl[i];
    }
    {
        int t0 = blockIdx.x;
        if (t0 < NTILES) {
            int row0 = t0 * 128;
            char* dsth = smc + SM_A;
            char* dstl = dsth + 128 * ATS_B;
            for (int i = tid; i < 128 * 16; i += 512) {
                int r = i >> 4, ch = (i & 15) * 16;
                int grow = row0 + r;
                int gz = (grow < NN) ? 0 : 16;
                int gr = (grow < NN) ? grow : 0;
                __pipeline_memcpy_async(dsth + r * ATS_B + ch,
                                        (const char*)(g_Ahi + gr * DD) + ch, 16, gz);
                __pipeline_memcpy_async(dstl + r * ATS_B + ch,
                                        (const char*)(g_Alo + gr * DD) + ch, 16, gz);
            }
        }
    }
    __pipeline_commit();
    __syncthreads();

    // ldmatrix per-lane offsets (proven R9 mappings)
    uint32_t a_loff = (uint32_t)(((lane & 15) * ATS + (lane >> 4) * 8) * 2);
    uint32_t b_loff = (uint32_t)((((lane & 7) + ((lane >> 4) & 1) * 8) * ATS
                                  + ((lane >> 3) & 1) * 8) * 2);
    uint32_t bhi_base = sb + SM_BHI + (uint32_t)(wn * 32 * ATS_B) + b_loff;
    uint32_t blo_base = sb + SM_BLO + (uint32_t)(wn * 32 * ATS_B) + b_loff;

    const float* bias = (const float*)(smc + SM_BIAS);
    const float* gam  = (const float*)(smc + SM_GAM);
    const float* bet  = (const float*)(smc + SM_BET);
    float2* lnp       = (float2*)(smc + SM_LNP);

    int l23 = lane >> 2;
    int lc  = (lane & 3) * 2;

    int buf = 0;
    for (int t = blockIdx.x; t < NTILES; t += gridDim.x) {
        int row0 = t * 128;
        __pipeline_wait_prior(0);
        __syncthreads();

        int tn = t + (int)gridDim.x;
        if (tn < NTILES) {
            int row0n = tn * 128;
            char* dsth = smc + SM_A + (buf ^ 1) * (2 * 128 * ATS_B);
            char* dstl = dsth + 128 * ATS_B;
            for (int i = tid; i < 128 * 16; i += 512) {
                int r = i >> 4, ch = (i & 15) * 16;
                int grow = row0n + r;
                int gz = (grow < NN) ? 0 : 16;
                int gr = (grow < NN) ? grow : 0;
                __pipeline_memcpy_async(dsth + r * ATS_B + ch,
                                        (const char*)(g_Ahi + gr * DD) + ch, 16, gz);
                __pipeline_memcpy_async(dstl + r * ATS_B + ch,
                                        (const char*)(g_Alo + gr * DD) + ch, 16, gz);
            }
        }
        __pipeline_commit();

        uint32_t abase_hi = sb + SM_A + (uint32_t)(buf * 2 * 128 * ATS_B) + a_loff
                          + (uint32_t)(wm * 32 * ATS_B);
        uint32_t abase_lo = abase_hi + (uint32_t)(128 * ATS_B);

        float acc[2][4][4];
#pragma unroll
        for (int mt = 0; mt < 2; ++mt)
#pragma unroll
            for (int nt = 0; nt < 4; ++nt)
#pragma unroll
                for (int e = 0; e < 4; ++e) acc[mt][nt][e] = 0.f;

#pragma unroll
        for (int ks = 0; ks < 8; ++ks) {
            uint32_t kofs = (uint32_t)(ks * 32);
            uint32_t bh00, bh01, bh02, bh03, bh10, bh11, bh12, bh13;
            uint32_t bl00, bl01, bl02, bl03, bl10, bl11, bl12, bl13;
            ldsm4(bh00, bh01, bh02, bh03, bhi_base + kofs);
            ldsm4(bh10, bh11, bh12, bh13, bhi_base + 16 * ATS_B + kofs);
            ldsm4(bl00, bl01, bl02, bl03, blo_base + kofs);
            ldsm4(bl10, bl11, bl12, bl13, blo_base + 16 * ATS_B + kofs);
#pragma unroll
            for (int mt = 0; mt < 2; ++mt) {
                uint32_t arow = (uint32_t)(mt * 16 * ATS_B) + kofs;
                uint32_t ah0, ah1, ah2, ah3, al0, al1, al2, al3;
                ldsm4(ah0, ah1, ah2, ah3, abase_hi + arow);
                ldsm4(al0, al1, al2, al3, abase_lo + arow);
                mma_bf16(acc[mt][0][0], acc[mt][0][1], acc[mt][0][2], acc[mt][0][3],
                         ah0, ah1, ah2, ah3, bh00, bh01);
                mma_bf16(acc[mt][0][0], acc[mt][0][1], acc[mt][0][2], acc[mt][0][3],
                         ah0, ah1, ah2, ah3, bl00, bl01);
                mma_bf16(acc[mt][0][0], acc[mt][0][1], acc[mt][0][2], acc[mt][0][3],
                         al0, al1, al2, al3, bh00, bh01);
                mma_bf16(acc[mt][1][0], acc[mt][1][1], acc[mt][1][2], acc[mt][1][3],
                         ah0, ah1, ah2, ah3, bh02, bh03);
                mma_bf16(acc[mt][1][0], acc[mt][1][1], acc[mt][1][2], acc[mt][1][3],
                         ah0, ah1, ah2, ah3, bl02, bl03);
                mma_bf16(acc[mt][1][0], acc[mt][1][1], acc[mt][1][2], acc[mt][1][3],
                         al0, al1, al2, al3, bh02, bh03);
                mma_bf16(acc[mt][2][0], acc[mt][2][1], acc[mt][2][2], acc[mt][2][3],
                         ah0, ah1, ah2, ah3, bh10, bh11);
                mma_bf16(acc[mt][2][0], acc[mt][2][1], acc[mt][2][2], acc[mt][2][3],
                         ah0, ah1, ah2, ah3, bl10, bl11);
                mma_bf16(acc[mt][2][0], acc[mt][2][1], acc[mt][2][2], acc[mt][2][3],
                         al0, al1, al2, al3, bh10, bh11);
                mma_bf16(acc[mt][3][0], acc[mt][3][1], acc[mt][3][2], acc[mt][3][3],
                         ah0, ah1, ah2, ah3, bh12, bh13);
                mma_bf16(acc[mt][3][0], acc[mt][3][1], acc[mt][3][2], acc[mt][3][3],
                         ah0, ah1, ah2, ah3, bl12, bl13);
                mma_bf16(acc[mt][3][0], acc[mt][3][1], acc[mt][3][2], acc[mt][3][3],
                         al0, al1, al2, al3, bh12, bh13);
            }
        }

        // ---- epilogue: bias (+residual), LN partials, normalize, store ----
#pragma unroll
        for (int mt = 0; mt < 2; ++mt) {
            int rl0 = wm * 32 + mt * 16 + l23;
            int rl1 = rl0 + 8;
            int gr0 = row0 + rl0, gr1 = row0 + rl1;
            int gc0 = (gr0 < NN) ? gr0 : 0;
            int gc1 = (gr1 < NN) ? gr1 : 0;
            float s0 = 0.f, q0 = 0.f, s1 = 0.f, q1 = 0.f;
#pragma unroll
            for (int nt = 0; nt < 4; ++nt) {
                int c = wn * 32 + nt * 8 + lc;
                float2 bv = *(const float2*)(bias + c);
                float v0 = acc[mt][nt][0] + bv.x;
                float v1 = acc[mt][nt][1] + bv.y;
                float v2 = acc[mt][nt][2] + bv.x;
                float v3 = acc[mt][nt][3] + bv.y;
                if (RES) {
                    float2 r0 = *(const float2*)&g_h[gc0 * DD + c];
                    float2 r1 = *(const float2*)&g_h[gc1 * DD + c];
                    v0 += r0.x; v1 += r0.y; v2 += r1.x; v3 += r1.y;
                }
                acc[mt][nt][0] = v0; acc[mt][nt][1] = v1;
                acc[mt][nt][2] = v2; acc[mt][nt][3] = v3;
                s0 += v0 + v1; q0 += v0 * v0 + v1 * v1;
                s1 += v2 + v3; q1 += v2 * v2 + v3 * v3;
            }
            s0 += __shfl_xor_sync(0xffffffffu, s0, 1); s0 += __shfl_xor_sync(0xffffffffu, s0, 2);
            q0 += __shfl_xor_sync(0xffffffffu, q0, 1); q0 += __shfl_xor_sync(0xffffffffu, q0, 2);
            s1 += __shfl_xor_sync(0xffffffffu, s1, 1); s1 += __shfl_xor_sync(0xffffffffu, s1, 2);
            q1 += __shfl_xor_sync(0xffffffffu, q1, 1); q1 += __shfl_xor_sync(0xffffffffu, q1, 2);
            if ((lane & 3) == 0) {
                lnp[rl0 * 4 + wn] = make_float2(s0, q0);
                lnp[rl1 * 4 + wn] = make_float2(s1, q1);
            }
        }
        __syncthreads();

#pragma unroll
        for (int mt = 0; mt < 2; ++mt) {
            int rl0 = wm * 32 + mt * 16 + l23;
            int rl1 = rl0 + 8;
            int gr0 = row0 + rl0, gr1 = row0 + rl1;
            float S0 = 0.f, Q0 = 0.f, S1 = 0.f, Q1 = 0.f;
#pragma unroll
            for (int w = 0; w < 4; ++w) {
                float2 p0 = lnp[rl0 * 4 + w]; S0 += p0.x; Q0 += p0.y;
                float2 p1 = lnp[rl1 * 4 + w]; S1 += p1.x; Q1 += p1.y;
            }
            float mu0 = S0 * (1.f / 128.f), mu1 = S1 * (1.f / 128.f);
            float rs0 = rsqrtf(Q0 * (1.f / 128.f) - mu0 * mu0 + 1e-5f);
            float rs1 = rsqrtf(Q1 * (1.f / 128.f) - mu1 * mu1 + 1e-5f);
#pragma unroll
            for (int nt = 0; nt < 4; ++nt) {
                int c = wn * 32 + nt * 8 + lc;
                float2 gv = *(const float2*)(gam + c);
                float2 tv = *(const float2*)(bet + c);
                float v0 = acc[mt][nt][0], v1 = acc[mt][nt][1];
                float v2 = acc[mt][nt][2], v3 = acc[mt][nt][3];
                float y0 = (v0 - mu0) * rs0 * gv.x + tv.x;
                float y1 = (v1 - mu0) * rs0 * gv.y + tv.y;
                float y2 = (v2 - mu1) * rs1 * gv.x + tv.x;
                float y3 = (v3 - mu1) * rs1 * gv.y + tv.y;
                if (gr0 < NN) {
                    if (FINAL) {
                        *(float2*)&dout[gr0 * DD + c] = make_float2(y0, y1);
                    } else {
                        *(float2*)&g_h [gr0 * DD + c] = make_float2(v0, v1);
                        *(float2*)&g_h2[gr0 * DD + c] = make_float2(fmaxf(y0, 0.f), fmaxf(y1, 0.f));
                    }
                }
                if (gr1 < NN) {
                    if (FINAL) {
                        *(float2*)&dout[gr1 * DD + c] = make_float2(y2, y3);
                    } else {
                        *(float2*)&g_h [gr1 * DD + c] = make_float2(v2, v3);
                        *(float2*)&g_h2[gr1 * DD + c] = make_float2(fmaxf(y2, 0.f), fmaxf(y3, 0.f));
                    }
                }
            }
        }
        buf ^= 1;
        __syncthreads();
    }
}

// ================= launch =====================================================
extern "C" void kernel_launch(void* const* d_in, const int* in_sizes, int n_in,
                              void* d_out, int out_size) {
    const int*   x    = (const int*)  d_in[0];
    const int*   ei   = (const int*)  d_in[1];
    const int*   ea   = (const int*)  d_in[2];
    const float* aemb = (const float*)d_in[3];
    const float* bemb = (const float*)d_in[4];
    const float* W    = (const float*)d_in[5];
    const float* b    = (const float*)d_in[6];
    const float* g    = (const float*)d_in[7];
    const float* bt   = (const float*)d_in[8];
    float* out = (float*)d_out;
    const int* src = ei;
    const int* dst = ei + EE;

    static float *p_h = nullptr, *p_h2 = nullptr;
    static __nv_bfloat16 *p_whi = nullptr, *p_wlo = nullptr;
    static int sms = 148;
    if (!p_h) {
        cudaGetSymbolAddress((void**)&p_h,   g_h);
        cudaGetSymbolAddress((void**)&p_h2,  g_h2);
        cudaGetSymbolAddress((void**)&p_whi, g_Whi);
        cudaGetSymbolAddress((void**)&p_wlo, g_Wlo);
        cudaDeviceGetAttribute(&sms, cudaDevAttrMultiProcessorCount, 0);
        cudaFuncSetAttribute((const void*)k_mma<false, false>, cudaFuncAttributeMaxDynamicSharedMemorySize, SM_TOTAL);
        cudaFuncSetAttribute((const void*)k_mma<true,  false>, cudaFuncAttributeMaxDynamicSharedMemorySize, SM_TOTAL);
        cudaFuncSetAttribute((const void*)k_mma<true,  true >, cudaFuncAttributeMaxDynamicSharedMemorySize, SM_TOTAL);
    }

    k_atom<<<(NN * 32 + 255) / 256, 256>>>(x, aemb, bemb);        // launch 0
    k_scatter<<<(EE + 255) / 256, 256>>>(src, dst, ea);           // launch 1
    k_wsplit<<<(7 * 128 * 32 + 255) / 256, 256>>>(W);             // launch 2

    int agg_blocks = sms * 5;
    for (int l = 0; l < 7; ++l) {
        const __nv_bfloat16* whl = p_whi + l * 128 * ATS;
        const __nv_bfloat16* wll = p_wlo + l * 128 * ATS;
        const float* bl  = b  + l * DD;
        const float* gl  = g  + l * DD;
        const float* btl = bt + l * DD;
        const float* hi = (l == 0) ? p_h : p_h2;
        k_agg<<<agg_blocks, 256>>>(hi);                           // launch 3 = agg0 (profiled)
        if (l == 0)
            k_mma<false, false><<<sms, 512, SM_TOTAL>>>(whl, wll, bl, gl, btl, out);
        else if (l < 6)
            k_mma<true, false><<<sms, 512, SM_TOTAL>>>(whl, wll, bl, gl, btl, out);
        else
            k_mma<true, true><<<sms, 512, SM_TOTAL>>>(whl, wll, bl, gl, btl, out);
    }
}